// round 1
// baseline (speedup 1.0000x reference)
#include <cuda_runtime.h>
#include <cuda_bf16.h>
#include <mma.h>
#include <cstdint>
#include <cstddef>

using namespace nvcuda;

#define N_NODES 50000
#define N_EDGES 800000
#define HDIM 128
#define LN_EPS 1e-5f
#define LDS_PAD 136            // padded smem leading dim (floats), multiple of 8

// Scratch (allocation-free rule: __device__ globals)
__device__ float g_xsxr[(size_t)N_NODES * 256];   // [n, 0:128]=x@Ws, [n,128:256]=x@Wr
__device__ float g_aggr[(size_t)N_NODES * HDIM];  // segment-sum accumulator

__device__ __forceinline__ float t32(float v) { return wmma::__float_to_tf32(v); }

__device__ __forceinline__ void red_add_v4(float* p, float a, float b, float c, float d) {
    asm volatile("red.global.add.v4.f32 [%0], {%1, %2, %3, %4};"
                 :: "l"(p), "f"(a), "f"(b), "f"(c), "f"(d) : "memory");
}

typedef wmma::fragment<wmma::matrix_a, 16, 16, 8, wmma::precision::tf32, wmma::row_major> FragA;
typedef wmma::fragment<wmma::matrix_b, 16, 16, 8, wmma::precision::tf32, wmma::row_major> FragB;
typedef wmma::fragment<wmma::accumulator, 16, 16, 8, float> FragC;

// ---------------------------------------------------------------------------
// Node projection: XsXr[:, cb*128 : cb*128+128] = x @ W1[cb*128 : cb*128+128, :]
// cb = blockIdx.y (0 -> Ws, 1 -> Wr). Tile 128 rows x 128 cols, K=128.
// ---------------------------------------------------------------------------
__global__ __launch_bounds__(512)
void nodeproj_kernel(const float* __restrict__ x, const float* __restrict__ W1) {
    extern __shared__ float smem[];
    float* sX = smem;                   // 128 x LDS_PAD (inputs, then accum output)
    float* sW = smem + 128 * LDS_PAD;   // 128 x LDS_PAD

    const int tid = threadIdx.x;
    const int rowBase = blockIdx.x * 128;
    const int cb = blockIdx.y;

    // stage x tile (tf32-rounded) and W block
    for (int f = tid; f < 128 * 32; f += 512) {
        int r = f >> 5, c = (f & 31) << 2;
        int gr = rowBase + r;
        float4 v = make_float4(0.f, 0.f, 0.f, 0.f);
        if (gr < N_NODES) v = *(const float4*)(x + (size_t)gr * HDIM + c);
        float* d = sX + r * LDS_PAD + c;
        d[0] = t32(v.x); d[1] = t32(v.y); d[2] = t32(v.z); d[3] = t32(v.w);

        float4 w = *(const float4*)(W1 + (size_t)(cb * 128 + r) * HDIM + c);
        float* dw = sW + r * LDS_PAD + c;
        dw[0] = t32(w.x); dw[1] = t32(w.y); dw[2] = t32(w.z); dw[3] = t32(w.w);
    }
    __syncthreads();

    const int w = tid >> 5;
    const int wr = w & 3;    // 4 row-blocks of 32
    const int wc = w >> 2;   // 4 col-blocks of 32

    FragC acc[2][2];
    #pragma unroll
    for (int i = 0; i < 2; ++i)
        #pragma unroll
        for (int j = 0; j < 2; ++j) wmma::fill_fragment(acc[i][j], 0.f);

    #pragma unroll
    for (int kk = 0; kk < 16; ++kk) {
        FragA a[2]; FragB b[2];
        #pragma unroll
        for (int i = 0; i < 2; ++i)
            wmma::load_matrix_sync(a[i], sX + (wr * 32 + i * 16) * LDS_PAD + kk * 8, LDS_PAD);
        #pragma unroll
        for (int j = 0; j < 2; ++j)
            wmma::load_matrix_sync(b[j], sW + (kk * 8) * LDS_PAD + wc * 32 + j * 16, LDS_PAD);
        #pragma unroll
        for (int i = 0; i < 2; ++i)
            #pragma unroll
            for (int j = 0; j < 2; ++j) wmma::mma_sync(acc[i][j], a[i], b[j], acc[i][j]);
    }
    __syncthreads();  // done reading sX before overwriting with accum

    #pragma unroll
    for (int i = 0; i < 2; ++i)
        #pragma unroll
        for (int j = 0; j < 2; ++j)
            wmma::store_matrix_sync(sX + (wr * 32 + i * 16) * LDS_PAD + wc * 32 + j * 16,
                                    acc[i][j], LDS_PAD, wmma::mem_row_major);
    __syncthreads();

    for (int f = tid; f < 128 * 32; f += 512) {
        int r = f >> 5, c = (f & 31) << 2;
        int gr = rowBase + r;
        if (gr < N_NODES) {
            float4 v = *(const float4*)(sX + r * LDS_PAD + c);
            *(float4*)(g_xsxr + (size_t)gr * 256 + cb * 128 + c) = v;
        }
    }
}

// ---------------------------------------------------------------------------
// Fused edge kernel (persistent): per 128-edge tile:
//   acc = edge_feat_tile @ We   (tf32 MMA, We smem-resident per block)
//   msg = relu(acc + Xs[s] + Xr[r] + b)
//   red.global.add.v4 into g_aggr[r]
// ---------------------------------------------------------------------------
__global__ __launch_bounds__(512)
void edge_kernel(const float* __restrict__ ef,
                 const int* __restrict__ senders,
                 const int* __restrict__ receivers,
                 const float* __restrict__ W1,
                 const float* __restrict__ b1) {
    extern __shared__ float smem[];
    float* sE = smem;                        // 128 x LDS_PAD (edge tile, then accum)
    float* sW = smem + 128 * LDS_PAD;        // 128 x LDS_PAD (We, tf32)
    float* sB = smem + 2 * 128 * LDS_PAD;    // 128 bias

    const int tid = threadIdx.x;
    const int w = tid >> 5;
    const int wr = w & 3;
    const int wc = w >> 2;

    // stage We = W1 rows [256, 384) and bias (once per block)
    for (int f = tid; f < 128 * 32; f += 512) {
        int k = f >> 5, c = (f & 31) << 2;
        float4 v = *(const float4*)(W1 + (size_t)(256 + k) * HDIM + c);
        float* d = sW + k * LDS_PAD + c;
        d[0] = t32(v.x); d[1] = t32(v.y); d[2] = t32(v.z); d[3] = t32(v.w);
    }
    for (int c = tid; c < HDIM; c += 512) sB[c] = b1[c];
    __syncthreads();

    const int nTiles = N_EDGES / 128;
    for (int tile = blockIdx.x; tile < nTiles; tile += gridDim.x) {
        const int base = tile * 128;

        for (int f = tid; f < 128 * 32; f += 512) {
            int r = f >> 5, c = (f & 31) << 2;
            float4 v = *(const float4*)(ef + (size_t)(base + r) * HDIM + c);
            float* d = sE + r * LDS_PAD + c;
            d[0] = t32(v.x); d[1] = t32(v.y); d[2] = t32(v.z); d[3] = t32(v.w);
        }
        __syncthreads();

        FragC acc[2][2];
        #pragma unroll
        for (int i = 0; i < 2; ++i)
            #pragma unroll
            for (int j = 0; j < 2; ++j) wmma::fill_fragment(acc[i][j], 0.f);

        #pragma unroll
        for (int kk = 0; kk < 16; ++kk) {
            FragA a[2]; FragB b[2];
            #pragma unroll
            for (int i = 0; i < 2; ++i)
                wmma::load_matrix_sync(a[i], sE + (wr * 32 + i * 16) * LDS_PAD + kk * 8, LDS_PAD);
            #pragma unroll
            for (int j = 0; j < 2; ++j)
                wmma::load_matrix_sync(b[j], sW + (kk * 8) * LDS_PAD + wc * 32 + j * 16, LDS_PAD);
            #pragma unroll
            for (int i = 0; i < 2; ++i)
                #pragma unroll
                for (int j = 0; j < 2; ++j) wmma::mma_sync(acc[i][j], a[i], b[j], acc[i][j]);
        }
        __syncthreads();

        #pragma unroll
        for (int i = 0; i < 2; ++i)
            #pragma unroll
            for (int j = 0; j < 2; ++j)
                wmma::store_matrix_sync(sE + (wr * 32 + i * 16) * LDS_PAD + wc * 32 + j * 16,
                                        acc[i][j], LDS_PAD, wmma::mem_row_major);
        __syncthreads();

        // epilogue: 4 threads per edge row, 32 cols each
        {
            const int row = tid >> 2;
            const int q = tid & 3;
            const int e = base + row;
            const int s = senders[e];
            const int rcv = receivers[e];
            const float4* xs = (const float4*)(g_xsxr + (size_t)s * 256);
            const float4* xr = (const float4*)(g_xsxr + (size_t)rcv * 256 + 128);
            const float4* ac = (const float4*)(sE + row * LDS_PAD);
            const float4* b4 = (const float4*)sB;
            float* dst = g_aggr + (size_t)rcv * HDIM;
            #pragma unroll
            for (int j = 0; j < 8; ++j) {
                int c4 = q * 8 + j;
                float4 m = ac[c4];
                float4 a_ = xs[c4];
                float4 r_ = xr[c4];
                float4 bb = b4[c4];
                float vx = fmaxf(m.x + a_.x + r_.x + bb.x, 0.f);
                float vy = fmaxf(m.y + a_.y + r_.y + bb.y, 0.f);
                float vz = fmaxf(m.z + a_.z + r_.z + bb.z, 0.f);
                float vw = fmaxf(m.w + a_.w + r_.w + bb.w, 0.f);
                red_add_v4(dst + c4 * 4, vx, vy, vz, vw);
            }
        }
        __syncthreads();
    }
}

// ---------------------------------------------------------------------------
// LayerNorm: out = gamma * (h - mu) * rsqrt(var + eps) + beta, h = aggr + x
// one warp per node
// ---------------------------------------------------------------------------
__global__ __launch_bounds__(256)
void ln_kernel(const float* __restrict__ x,
               const float* __restrict__ gamma,
               const float* __restrict__ beta,
               float* __restrict__ out) {
    const int gwarp = (blockIdx.x * blockDim.x + threadIdx.x) >> 5;
    const int lane = threadIdx.x & 31;
    if (gwarp >= N_NODES) return;

    const int c = lane * 4;
    float4 ag = *(const float4*)(g_aggr + (size_t)gwarp * HDIM + c);
    float4 xv = *(const float4*)(x + (size_t)gwarp * HDIM + c);
    float4 h = make_float4(ag.x + xv.x, ag.y + xv.y, ag.z + xv.z, ag.w + xv.w);

    float s = h.x + h.y + h.z + h.w;
    float ss = h.x * h.x + h.y * h.y + h.z * h.z + h.w * h.w;
    #pragma unroll
    for (int off = 16; off > 0; off >>= 1) {
        s += __shfl_xor_sync(0xffffffff, s, off);
        ss += __shfl_xor_sync(0xffffffff, ss, off);
    }
    const float mean = s * (1.f / HDIM);
    const float var = ss * (1.f / HDIM) - mean * mean;
    const float inv = rsqrtf(var + LN_EPS);

    float4 g = *(const float4*)(gamma + c);
    float4 b = *(const float4*)(beta + c);
    float4 o;
    o.x = g.x * (h.x - mean) * inv + b.x;
    o.y = g.y * (h.y - mean) * inv + b.y;
    o.z = g.z * (h.z - mean) * inv + b.z;
    o.w = g.w * (h.w - mean) * inv + b.w;
    *(float4*)(out + (size_t)gwarp * HDIM + c) = o;
}

// ---------------------------------------------------------------------------
extern "C" void kernel_launch(void* const* d_in, const int* in_sizes, int n_in,
                              void* d_out, int out_size) {
    const float* x        = (const float*)d_in[0];
    const int*   senders  = (const int*)d_in[1];
    const int*   receivers= (const int*)d_in[2];
    const float* ef       = (const float*)d_in[3];
    const float* W1       = (const float*)d_in[4];
    const float* b1       = (const float*)d_in[5];
    const float* gamma    = (const float*)d_in[6];
    const float* beta     = (const float*)d_in[7];
    float* out = (float*)d_out;

    void* aggr_ptr = nullptr;
    cudaGetSymbolAddress(&aggr_ptr, g_aggr);
    cudaMemsetAsync(aggr_ptr, 0, (size_t)N_NODES * HDIM * sizeof(float), 0);

    const size_t smem_np = (size_t)2 * 128 * LDS_PAD * sizeof(float);
    const size_t smem_ed = smem_np + 128 * sizeof(float);
    cudaFuncSetAttribute(nodeproj_kernel, cudaFuncAttributeMaxDynamicSharedMemorySize, (int)smem_np);
    cudaFuncSetAttribute(edge_kernel, cudaFuncAttributeMaxDynamicSharedMemorySize, (int)smem_ed);

    nodeproj_kernel<<<dim3((N_NODES + 127) / 128, 2), 512, smem_np>>>(x, W1);
    edge_kernel<<<152, 512, smem_ed>>>(ef, senders, receivers, W1, b1);
    ln_kernel<<<(N_NODES + 7) / 8, 256>>>(x, gamma, beta, out);
}